// round 10
// baseline (speedup 1.0000x reference)
#include <cuda_runtime.h>

#define Bn   16
#define Tn   262144
#define HOP  256
#define WINL 1024
#define PADL 384
#define Fn   1024
#define Pn   22
#define NGRP 512            // frame groups (32 frames each)
#define SPAN 8960           // per-group OLA span
#define STRIPL 768          // seam width
#define NCHUNK 16           // chunks computed per warp (balanced 3-way split)
#define WARM_CHUNKS 8       // 256-sample warm-up (verified safe in R6)

// Cross-group seam partial sums
__device__ float d_strip_lo[NGRP][STRIPL];
__device__ float d_strip_hi[NGRP][STRIPL];

typedef unsigned long long ull;

static __device__ __forceinline__ ull pk2(float lo, float hi) {
    ull r; asm("mov.b64 %0,{%1,%2};" : "=l"(r) : "f"(lo), "f"(hi)); return r;
}
static __device__ __forceinline__ void upk2(float& lo, float& hi, ull v) {
    asm("mov.b64 {%0,%1},%2;" : "=f"(lo), "=f"(hi) : "l"(v));
}
static __device__ __forceinline__ ull fma2_(ull a, ull b, ull c) {
    ull r; asm("fma.rn.f32x2 %0,%1,%2,%3;" : "=l"(r) : "l"(a), "l"(b), "l"(c)); return r;
}
static __device__ __forceinline__ ull mul2_(ull a, ull b) {
    ull r; asm("mul.rn.f32x2 %0,%1,%2;" : "=l"(r) : "l"(a), "l"(b)); return r;
}
static __device__ __forceinline__ ull add2_(ull a, ull b) {
    ull r; asm("add.rn.f32x2 %0,%1,%2;" : "=l"(r) : "l"(a), "l"(b)); return r;
}

static __device__ __forceinline__ float hannf(int t) {
    return 0.5f - 0.5f * __cosf(6.283185307179586f * (float)t * (1.0f / 1024.0f));
}

// smem (floats): acc[SPAN] | buf[3 warps][32*34]  (buf = x stage AND y tile)
#define BUF_F 1088
#define SMEM_FLOATS (SPAN + 3 * BUF_F)
#define SMEM_BYTES  (SMEM_FLOATS * 4)   // 48896 B -> 4 CTAs/SM

// ---------------------------------------------------------------------------
// Kernel 1: one CTA (96 threads = 3 warps) per 32-frame group.
//   Balanced 3-way time split, 16 chunks computed per warp:
//     warp w computes absolute chunks 8w..8w+15 (t0 = 256w + 32cc);
//     warps 1..2 discard first 8 chunks (256-sample warm-up).
//   OLA is done COOPERATIVELY per round, partitioned by acc cell-block k
//   (k*256 + 32cc + lane), so no two threads ever touch the same cell: the
//   per-warp += scheme raced whenever t0s collided mod 256 (R8/R9 failures).
// ---------------------------------------------------------------------------
__global__ void __launch_bounds__(96)
lpc_ola_kernel(const float* __restrict__ ex,
               const float* __restrict__ gain,
               const float* __restrict__ a,
               float* __restrict__ out) {
    extern __shared__ float smem[];

    const int warp = threadIdx.x >> 5;        // segment 0..2
    const int lane = threadIdx.x & 31;
    const int gw   = blockIdx.x;               // frame group 0..511
    const int s0   = gw * 32;
    const int s    = s0 + lane;                 // this lane's sequence
    const int b    = s >> 10;
    const int ww   = gw & 31;                   // group index within batch
    const int f0   = ww * 32;                   // base frame

    float* __restrict__ acc  = smem;
    float* __restrict__ bufs = smem + SPAN;             // base of 3 warp bufs
    float* __restrict__ buf  = bufs + warp * BUF_F;     // this warp's buf

    // zero shared accumulator
    for (int i = threadIdx.x; i < SPAN / 4; i += 96)
        ((float4*)acc)[i] = make_float4(0.f, 0.f, 0.f, 0.f);

    const float g = gain[s];

    // c[q] = -a[q-1] (q=1..22), c[23]=c[24]=0
    float c[25];
    #pragma unroll
    for (int p = 0; p < Pn; ++p) c[p + 1] = -a[s * Pn + p];
    c[23] = 0.0f; c[24] = 0.0f;
    const float c1 = c[1];

    // CA[k] = (c_{2k+1}, c_{2k+2}) : y0 dot
    // CE[k] = (c_{2k+2}, c_{2k+3}) : y1 shifted dot (y1 = c1*y0 + g*x1 + dotE)
    ull CA[11], CE[11], H[11];
    #pragma unroll
    for (int k = 0; k < 11; ++k) {
        CA[k] = pk2(c[2 * k + 1], c[2 * k + 2]);
        CE[k] = pk2(c[2 * k + 2], c[2 * k + 3]);
        H[k]  = 0ull;
    }
    __syncthreads();

    const float* __restrict__ exb = ex + b * Tn;
    const int tbase = warp * 256;               // absolute chunks 8w..

    // prefetch chunk 0 (coalesced: lane sweeps time, r sweeps frames)
    float xr[32];
    #pragma unroll
    for (int r = 0; r < 32; ++r) {
        int idx = (f0 + r) * HOP + tbase + lane - PADL;
        xr[r] = ((unsigned)idx < (unsigned)Tn) ? exb[idx] : 0.0f;
    }

    for (int cc = 0; cc < NCHUNK; ++cc) {
        const int t0 = tbase + 32 * cc;

        // commit prefetched chunk to this warp's buffer
        #pragma unroll
        for (int r = 0; r < 32; ++r) buf[r * 34 + lane] = xr[r];
        __syncwarp();

        // prefetch next chunk; latency hides under recurrence
        if (cc < NCHUNK - 1) {
            const int t1 = t0 + 32;
            #pragma unroll
            for (int r = 0; r < 32; ++r) {
                int idx = (f0 + r) * HOP + t1 + lane - PADL;
                xr[r] = ((unsigned)idx < (unsigned)Tn) ? exb[idx] : 0.0f;
            }
        }

        // 16 blocks x 2 samples; buf row is consumed and overwritten in place
        float* xrow = buf + lane * 34;
        float2 xp2 = *(const float2*)xrow;
        #pragma unroll
        for (int bk = 0; bk < 16; ++bk) {
            float2 xn2;
            if (bk < 15) xn2 = *(const float2*)(xrow + 2 * bk + 2);
            const float x0 = xp2.x, x1 = xp2.y;

            // even/odd split packed dots, H[0] last
            ull ae = mul2_(CA[10], H[10]);
            ae = fma2_(CA[8], H[8], ae);
            ae = fma2_(CA[6], H[6], ae);
            ae = fma2_(CA[4], H[4], ae);
            ae = fma2_(CA[2], H[2], ae);
            ull ao = mul2_(CA[9], H[9]);
            ao = fma2_(CA[7], H[7], ao);
            ao = fma2_(CA[5], H[5], ao);
            ao = fma2_(CA[3], H[3], ao);
            ao = fma2_(CA[1], H[1], ao);
            ae = fma2_(CA[0], H[0], ae);
            const ull accA = add2_(ae, ao);

            ull ee = mul2_(CE[10], H[10]);
            ee = fma2_(CE[8], H[8], ee);
            ee = fma2_(CE[6], H[6], ee);
            ee = fma2_(CE[4], H[4], ee);
            ee = fma2_(CE[2], H[2], ee);
            ull eo = mul2_(CE[9], H[9]);
            eo = fma2_(CE[7], H[7], eo);
            eo = fma2_(CE[5], H[5], eo);
            eo = fma2_(CE[3], H[3], eo);
            eo = fma2_(CE[1], H[1], eo);
            ee = fma2_(CE[0], H[0], ee);
            const ull accE = add2_(ee, eo);

            float aLo, aHi, eLo, eHi;
            upk2(aLo, aHi, accA);
            upk2(eLo, eHi, accE);
            const float y0 = fmaf(g, x0, aLo + aHi);
            const float y1 = fmaf(c1, y0, fmaf(g, x1, eLo + eHi));

            *(float2*)(xrow + 2 * bk) = make_float2(y0, y1);

            #pragma unroll
            for (int k = 10; k > 0; --k) H[k] = H[k - 1];
            H[0] = pk2(y1, y0);

            xp2 = xn2;
        }
        __syncthreads();   // all 3 warps' y tiles for this round are ready

        // cooperative, race-free OLA: cell block k owned by warp (k mod 3)
        // warp w' contributes its row r = k - w' (its t0 = 256w' + 32cc)
        const float wf0 = hannf(32 * cc + lane);
        const float wf1 = hannf(256 + 32 * cc + lane);
        const float wf2 = hannf(512 + 32 * cc + lane);
        const bool emit12 = (cc >= WARM_CHUNKS);
        const int kmax = emit12 ? 34 : 32;
        for (int k = warp; k < kmax; k += 3) {
            float sum = 0.0f;
            if (k < 32)
                sum = bufs[k * 34 + lane] * wf0;
            if (emit12) {
                const int r1 = k - 1;
                if ((unsigned)r1 < 32u)
                    sum += bufs[BUF_F + r1 * 34 + lane] * wf1;
                const int r2 = k - 2;
                if ((unsigned)r2 < 32u)
                    sum += bufs[2 * BUF_F + r2 * 34 + lane] * wf2;
            }
            acc[k * 256 + 32 * cc + lane] += sum;
        }
        __syncthreads();   // before next round overwrites the bufs
    }

    // interior [768, 8192): all 4 contributions local; norm == 2 exactly
    float* __restrict__ outb = out + (size_t)b * Tn + ww * 8192 + 384;
    const float4* __restrict__ acc4 = (const float4*)(acc + STRIPL);
    for (int i = threadIdx.x; i < (8192 - STRIPL) / 4; i += 96) {
        float4 v = acc4[i];
        v.x *= 0.5f; v.y *= 0.5f; v.z *= 0.5f; v.w *= 0.5f;
        ((float4*)outb)[i] = v;
    }
    // seams for kernel 2
    for (int j = threadIdx.x; j < STRIPL; j += 96) {
        d_strip_lo[gw][j] = acc[j];
        d_strip_hi[gw][j] = acc[8192 + j];
    }
}

// ---------------------------------------------------------------------------
// Kernel 2: resolve seams. One block per region, 192 threads, float4/thread.
//   Non-edge seams have norm == 2 exactly; batch edges use hann norms.
// ---------------------------------------------------------------------------
__global__ void __launch_bounds__(192)
strip_kernel(float* __restrict__ out) {
    const int rg = blockIdx.x;
    const int q  = threadIdx.x;        // float4 index 0..191

    if (rg < NGRP) {
        const int w  = rg;
        const int ww = w & 31;
        const int bI = w >> 5;
        const int pbase = ww * 8192;
        const float4 lo4 = ((const float4*)d_strip_lo[w])[q];
        if (ww > 0) {                  // interior seam: norm exactly 2
            const float4 hi4 = ((const float4*)d_strip_hi[w - 1])[q];
            float4 v;
            v.x = (lo4.x + hi4.x) * 0.5f;
            v.y = (lo4.y + hi4.y) * 0.5f;
            v.z = (lo4.z + hi4.z) * 0.5f;
            v.w = (lo4.w + hi4.w) * 0.5f;
            *(float4*)(out + (size_t)bI * Tn + pbase + 4 * q - PADL) = v;
            return;
        }
        // batch-leading edge: per element with window norms
        const float sv[4] = {lo4.x, lo4.y, lo4.z, lo4.w};
        #pragma unroll
        for (int e = 0; e < 4; ++e) {
            const int p = pbase + 4 * q + e;
            const int o = p - PADL;
            if ((unsigned)o >= (unsigned)Tn) continue;
            const int fhi = p >> 8;
            float norm = 0.0f;
            #pragma unroll
            for (int k = 0; k < 4; ++k) {
                const int ff = fhi - k;
                if (ff >= 0 && ff < Fn) norm += hannf(p - ff * HOP);
            }
            out[(size_t)bI * Tn + o] = sv[e] / norm;
        }
    } else {
        const int w = ((rg - NGRP) << 5) | 31;   // batch-trailing edge
        const int bI = w >> 5;
        const int pbase = 32 * 8192;
        const float4 hi4 = ((const float4*)d_strip_hi[w])[q];
        const float sv[4] = {hi4.x, hi4.y, hi4.z, hi4.w};
        #pragma unroll
        for (int e = 0; e < 4; ++e) {
            const int p = pbase + 4 * q + e;
            const int o = p - PADL;
            if ((unsigned)o >= (unsigned)Tn) continue;
            const int fhi = p >> 8;
            float norm = 0.0f;
            #pragma unroll
            for (int k = 0; k < 4; ++k) {
                const int ff = fhi - k;
                if (ff >= 0 && ff < Fn) norm += hannf(p - ff * HOP);
            }
            out[(size_t)bI * Tn + o] = sv[e] / norm;
        }
    }
}

// ---------------------------------------------------------------------------
extern "C" void kernel_launch(void* const* d_in, const int* in_sizes, int n_in,
                              void* d_out, int out_size) {
    const float* ex   = (const float*)d_in[0];
    const float* gain = (const float*)d_in[1];
    const float* a    = (const float*)d_in[2];
    float* out = (float*)d_out;

    cudaFuncSetAttribute(lpc_ola_kernel,
                         cudaFuncAttributeMaxDynamicSharedMemorySize, SMEM_BYTES);
    lpc_ola_kernel<<<NGRP, 96, SMEM_BYTES>>>(ex, gain, a, out);
    strip_kernel<<<NGRP + Bn, 192>>>(out);
}

// round 11
// speedup vs baseline: 1.2526x; 1.2526x over previous
#include <cuda_runtime.h>

#define Bn   16
#define Tn   262144
#define HOP  256
#define WINL 1024
#define PADL 384
#define Fn   1024
#define Pn   22
#define NGRP 512            // frame groups (32 frames each)
#define SPAN 8960           // per-group OLA span
#define STRIPL 768          // seam width
#define NCHUNK 18           // chunks computed per warp (offsets 0/320/448)

// Cross-group seam partial sums
__device__ float d_strip_lo[NGRP][STRIPL];
__device__ float d_strip_hi[NGRP][STRIPL];

typedef unsigned long long ull;

static __device__ __forceinline__ ull pk2(float lo, float hi) {
    ull r; asm("mov.b64 %0,{%1,%2};" : "=l"(r) : "f"(lo), "f"(hi)); return r;
}
static __device__ __forceinline__ void upk2(float& lo, float& hi, ull v) {
    asm("mov.b64 {%0,%1},%2;" : "=f"(lo), "=f"(hi) : "l"(v));
}
static __device__ __forceinline__ ull fma2_(ull a, ull b, ull c) {
    ull r; asm("fma.rn.f32x2 %0,%1,%2,%3;" : "=l"(r) : "l"(a), "l"(b), "l"(c)); return r;
}
static __device__ __forceinline__ ull mul2_(ull a, ull b) {
    ull r; asm("mul.rn.f32x2 %0,%1,%2;" : "=l"(r) : "l"(a), "l"(b)); return r;
}
static __device__ __forceinline__ ull add2_(ull a, ull b) {
    ull r; asm("add.rn.f32x2 %0,%1,%2;" : "=l"(r) : "l"(a), "l"(b)); return r;
}

static __device__ __forceinline__ float hannf(int t) {
    return 0.5f - 0.5f * __cosf(6.283185307179586f * (float)t * (1.0f / 1024.0f));
}

// smem (floats): acc[SPAN] | buf[3 warps][32*34]  (buf = x stage AND y tile)
#define BUF_F 1088
#define SMEM_FLOATS (SPAN + 3 * BUF_F)
#define SMEM_BYTES  (SMEM_FLOATS * 4)   // 48896 B -> 4 CTAs/SM

// ---------------------------------------------------------------------------
// Kernel 1: one CTA (96 threads = 3 warps) per 32-frame group.
//   Time-split with RACE-FREE-BY-GEOMETRY offsets (0, 320, 448):
//     warp0 computes t [0,576),   emits [0,576)            (18 chunks)
//     warp1 computes t [320,896), emits [576,896), warm 256 (18 chunks)
//     warp2 computes t [448,1024),emits [896,1024),warm 448 (18 chunks)
//   OLA collision requires concurrent round-skew >= 2 (pairwise block offsets
//   mod 256 are {2,6,4} x32); one __syncthreads every 2 rounds bounds skew
//   to <= 1  => no cell is ever touched by two warps concurrently.
// ---------------------------------------------------------------------------
__global__ void __launch_bounds__(96)
lpc_ola_kernel(const float* __restrict__ ex,
               const float* __restrict__ gain,
               const float* __restrict__ a,
               float* __restrict__ out) {
    extern __shared__ float smem[];

    const int warp = threadIdx.x >> 5;        // segment 0..2
    const int lane = threadIdx.x & 31;
    const int gw   = blockIdx.x;               // frame group 0..511
    const int s0   = gw * 32;
    const int s    = s0 + lane;                 // this lane's sequence
    const int b    = s >> 10;
    const int ww   = gw & 31;                   // group index within batch
    const int f0   = ww * 32;                   // base frame

    float* __restrict__ acc = smem;
    float* __restrict__ buf = smem + SPAN + warp * BUF_F;

    // zero shared accumulator
    for (int i = threadIdx.x; i < SPAN / 4; i += 96)
        ((float4*)acc)[i] = make_float4(0.f, 0.f, 0.f, 0.f);

    const float g = gain[s];

    // c[q] = -a[q-1] (q=1..22), c[23]=c[24]=0
    float c[25];
    #pragma unroll
    for (int p = 0; p < Pn; ++p) c[p + 1] = -a[s * Pn + p];
    c[23] = 0.0f; c[24] = 0.0f;
    const float c1 = c[1];

    // CA[k] = (c_{2k+1}, c_{2k+2}) : y0 dot
    // CE[k] = (c_{2k+2}, c_{2k+3}) : y1 shifted dot (y1 = c1*y0 + g*x1 + dotE)
    ull CA[11], CE[11], H[11];
    #pragma unroll
    for (int k = 0; k < 11; ++k) {
        CA[k] = pk2(c[2 * k + 1], c[2 * k + 2]);
        CE[k] = pk2(c[2 * k + 2], c[2 * k + 3]);
        H[k]  = 0ull;
    }
    __syncthreads();

    const float* __restrict__ exb = ex + b * Tn;
    const int tbase      = (warp == 0) ? 0 : (warp == 1 ? 320 : 448);
    const int emit_start = (warp == 0) ? 0 : (warp == 1 ? 8   : 14);

    // prefetch chunk 0 (coalesced: lane sweeps time, r sweeps frames)
    float xr[32];
    #pragma unroll
    for (int r = 0; r < 32; ++r) {
        int idx = (f0 + r) * HOP + tbase + lane - PADL;
        xr[r] = ((unsigned)idx < (unsigned)Tn) ? exb[idx] : 0.0f;
    }

    for (int cc = 0; cc < NCHUNK; ++cc) {
        const int t0 = tbase + 32 * cc;

        // commit prefetched chunk to this warp's buffer
        #pragma unroll
        for (int r = 0; r < 32; ++r) buf[r * 34 + lane] = xr[r];
        __syncwarp();

        // prefetch next chunk; latency hides under recurrence
        if (cc < NCHUNK - 1) {
            const int t1 = t0 + 32;
            #pragma unroll
            for (int r = 0; r < 32; ++r) {
                int idx = (f0 + r) * HOP + t1 + lane - PADL;
                xr[r] = ((unsigned)idx < (unsigned)Tn) ? exb[idx] : 0.0f;
            }
        }

        // 16 blocks x 2 samples; buf row is consumed and overwritten in place
        float* xrow = buf + lane * 34;
        float2 xp2 = *(const float2*)xrow;
        #pragma unroll
        for (int bk = 0; bk < 16; ++bk) {
            float2 xn2;
            if (bk < 15) xn2 = *(const float2*)(xrow + 2 * bk + 2);
            const float x0 = xp2.x, x1 = xp2.y;

            // even/odd split packed dots, H[0] last
            ull ae = mul2_(CA[10], H[10]);
            ae = fma2_(CA[8], H[8], ae);
            ae = fma2_(CA[6], H[6], ae);
            ae = fma2_(CA[4], H[4], ae);
            ae = fma2_(CA[2], H[2], ae);
            ull ao = mul2_(CA[9], H[9]);
            ao = fma2_(CA[7], H[7], ao);
            ao = fma2_(CA[5], H[5], ao);
            ao = fma2_(CA[3], H[3], ao);
            ao = fma2_(CA[1], H[1], ao);
            ae = fma2_(CA[0], H[0], ae);
            const ull accA = add2_(ae, ao);

            ull ee = mul2_(CE[10], H[10]);
            ee = fma2_(CE[8], H[8], ee);
            ee = fma2_(CE[6], H[6], ee);
            ee = fma2_(CE[4], H[4], ee);
            ee = fma2_(CE[2], H[2], ee);
            ull eo = mul2_(CE[9], H[9]);
            eo = fma2_(CE[7], H[7], eo);
            eo = fma2_(CE[5], H[5], eo);
            eo = fma2_(CE[3], H[3], eo);
            eo = fma2_(CE[1], H[1], eo);
            ee = fma2_(CE[0], H[0], ee);
            const ull accE = add2_(ee, eo);

            float aLo, aHi, eLo, eHi;
            upk2(aLo, aHi, accA);
            upk2(eLo, eHi, accE);
            const float y0 = fmaf(g, x0, aLo + aHi);
            const float y1 = fmaf(c1, y0, fmaf(g, x1, eLo + eHi));

            *(float2*)(xrow + 2 * bk) = make_float2(y0, y1);

            #pragma unroll
            for (int k = 10; k > 0; --k) H[k] = H[k - 1];
            H[0] = pk2(y1, y0);

            xp2 = xn2;
        }
        __syncwarp();

        // per-warp windowed OLA accumulate (emit range only); geometry +
        // the every-2-rounds barrier below make this provably race-free
        if (cc >= emit_start) {
            const float wv = hannf(t0 + lane);
            #pragma unroll
            for (int r = 0; r < 32; ++r)
                acc[r * HOP + t0 + lane] += buf[r * 34 + lane] * wv;
        }
        __syncwarp();

        if (cc & 1) __syncthreads();   // bound concurrent OLA skew to <= 1
    }
    __syncthreads();

    // interior [768, 8192): all 4 contributions local; norm == 2 exactly
    float* __restrict__ outb = out + (size_t)b * Tn + ww * 8192 + 384;
    const float4* __restrict__ acc4 = (const float4*)(acc + STRIPL);
    for (int i = threadIdx.x; i < (8192 - STRIPL) / 4; i += 96) {
        float4 v = acc4[i];
        v.x *= 0.5f; v.y *= 0.5f; v.z *= 0.5f; v.w *= 0.5f;
        ((float4*)outb)[i] = v;
    }
    // seams for kernel 2
    for (int j = threadIdx.x; j < STRIPL; j += 96) {
        d_strip_lo[gw][j] = acc[j];
        d_strip_hi[gw][j] = acc[8192 + j];
    }
}

// ---------------------------------------------------------------------------
// Kernel 2: resolve seams. One block per region, 192 threads, float4/thread.
//   Non-edge seams have norm == 2 exactly; batch edges use hann norms.
// ---------------------------------------------------------------------------
__global__ void __launch_bounds__(192)
strip_kernel(float* __restrict__ out) {
    const int rg = blockIdx.x;
    const int q  = threadIdx.x;        // float4 index 0..191

    if (rg < NGRP) {
        const int w  = rg;
        const int ww = w & 31;
        const int bI = w >> 5;
        const int pbase = ww * 8192;
        const float4 lo4 = ((const float4*)d_strip_lo[w])[q];
        if (ww > 0) {                  // interior seam: norm exactly 2
            const float4 hi4 = ((const float4*)d_strip_hi[w - 1])[q];
            float4 v;
            v.x = (lo4.x + hi4.x) * 0.5f;
            v.y = (lo4.y + hi4.y) * 0.5f;
            v.z = (lo4.z + hi4.z) * 0.5f;
            v.w = (lo4.w + hi4.w) * 0.5f;
            *(float4*)(out + (size_t)bI * Tn + pbase + 4 * q - PADL) = v;
            return;
        }
        // batch-leading edge: per element with window norms
        const float sv[4] = {lo4.x, lo4.y, lo4.z, lo4.w};
        #pragma unroll
        for (int e = 0; e < 4; ++e) {
            const int p = pbase + 4 * q + e;
            const int o = p - PADL;
            if ((unsigned)o >= (unsigned)Tn) continue;
            const int fhi = p >> 8;
            float norm = 0.0f;
            #pragma unroll
            for (int k = 0; k < 4; ++k) {
                const int ff = fhi - k;
                if (ff >= 0 && ff < Fn) norm += hannf(p - ff * HOP);
            }
            out[(size_t)bI * Tn + o] = sv[e] / norm;
        }
    } else {
        const int w = ((rg - NGRP) << 5) | 31;   // batch-trailing edge
        const int bI = w >> 5;
        const int pbase = 32 * 8192;
        const float4 hi4 = ((const float4*)d_strip_hi[w])[q];
        const float sv[4] = {hi4.x, hi4.y, hi4.z, hi4.w};
        #pragma unroll
        for (int e = 0; e < 4; ++e) {
            const int p = pbase + 4 * q + e;
            const int o = p - PADL;
            if ((unsigned)o >= (unsigned)Tn) continue;
            const int fhi = p >> 8;
            float norm = 0.0f;
            #pragma unroll
            for (int k = 0; k < 4; ++k) {
                const int ff = fhi - k;
                if (ff >= 0 && ff < Fn) norm += hannf(p - ff * HOP);
            }
            out[(size_t)bI * Tn + o] = sv[e] / norm;
        }
    }
}

// ---------------------------------------------------------------------------
extern "C" void kernel_launch(void* const* d_in, const int* in_sizes, int n_in,
                              void* d_out, int out_size) {
    const float* ex   = (const float*)d_in[0];
    const float* gain = (const float*)d_in[1];
    const float* a    = (const float*)d_in[2];
    float* out = (float*)d_out;

    cudaFuncSetAttribute(lpc_ola_kernel,
                         cudaFuncAttributeMaxDynamicSharedMemorySize, SMEM_BYTES);
    lpc_ola_kernel<<<NGRP, 96, SMEM_BYTES>>>(ex, gain, a, out);
    strip_kernel<<<NGRP + Bn, 192>>>(out);
}

// round 12
// speedup vs baseline: 1.5533x; 1.2400x over previous
#include <cuda_runtime.h>

#define Bn   16
#define Tn   262144
#define HOP  256
#define WINL 1024
#define PADL 384
#define Fn   1024
#define Pn   22
#define NGRP 512            // frame groups (32 frames each)
#define SPAN 8960           // per-group OLA span
#define STRIPL 768          // seam width
#define NCHUNK 20           // chunks computed per warp (offsets 0 / 384)
#define EMIT1  8            // warp1 emits from chunk 8 (256-sample warm-up)

// Cross-group seam partial sums
__device__ float d_strip_lo[NGRP][STRIPL];
__device__ float d_strip_hi[NGRP][STRIPL];

typedef unsigned long long ull;

static __device__ __forceinline__ ull pk2(float lo, float hi) {
    ull r; asm("mov.b64 %0,{%1,%2};" : "=l"(r) : "f"(lo), "f"(hi)); return r;
}
static __device__ __forceinline__ void upk2(float& lo, float& hi, ull v) {
    asm("mov.b64 {%0,%1},%2;" : "=f"(lo), "=f"(hi) : "l"(v));
}
static __device__ __forceinline__ ull fma2_(ull a, ull b, ull c) {
    ull r; asm("fma.rn.f32x2 %0,%1,%2,%3;" : "=l"(r) : "l"(a), "l"(b), "l"(c)); return r;
}
static __device__ __forceinline__ ull mul2_(ull a, ull b) {
    ull r; asm("mul.rn.f32x2 %0,%1,%2;" : "=l"(r) : "l"(a), "l"(b)); return r;
}
static __device__ __forceinline__ ull add2_(ull a, ull b) {
    ull r; asm("add.rn.f32x2 %0,%1,%2;" : "=l"(r) : "l"(a), "l"(b)); return r;
}

static __device__ __forceinline__ float hannf(int t) {
    return 0.5f - 0.5f * __cosf(6.283185307179586f * (float)t * (1.0f / 1024.0f));
}

// smem (floats): acc[SPAN] | buf[2 warps][32*36] (buf = x stage AND y tile)
#define BUFSTRIDE 36        // 144B rows: 16B-aligned float4 access per lane
#define BUF_F (32 * BUFSTRIDE)
#define SMEM_FLOATS (SPAN + 2 * BUF_F)
#define SMEM_BYTES  (SMEM_FLOATS * 4)   // 45056 B

// ---------------------------------------------------------------------------
// Kernel 1: one CTA (64 threads = 2 warps) per 32-frame group.
//   warp0: computes t [0,640),   emits [0,640)
//   warp1: computes t [384,1024),emits [640,1024)  (256-sample warm-up)
//   OLA race-freedom: block offsets mod 256 differ by 4x32 => collision needs
//   round-skew == 4 (mod 8); __syncthreads every 4 rounds bounds skew <= 3.
//   Recurrence: 4-sample blocks. y2/y3 dots reuse CA/CE shifted by ONE PAIR:
//     y2 dot = sum_k CA[k+1].H[k],  y3 dot = sum_k CE[k+1].H[k]
//   so no extra coefficient registers; history shift = 9 MOV64 per 4 samples.
// ---------------------------------------------------------------------------
__global__ void __launch_bounds__(64)
lpc_ola_kernel(const float* __restrict__ ex,
               const float* __restrict__ gain,
               const float* __restrict__ a,
               float* __restrict__ out) {
    extern __shared__ float smem[];

    const int warp = threadIdx.x >> 5;        // segment 0..1
    const int lane = threadIdx.x & 31;
    const int gw   = blockIdx.x;               // frame group 0..511
    const int s0   = gw * 32;
    const int s    = s0 + lane;                 // this lane's sequence
    const int b    = s >> 10;
    const int ww   = gw & 31;                   // group index within batch
    const int f0   = ww * 32;                   // base frame

    float* __restrict__ acc = smem;
    float* __restrict__ buf = smem + SPAN + warp * BUF_F;

    // zero shared accumulator
    for (int i = threadIdx.x; i < SPAN / 4; i += 64)
        ((float4*)acc)[i] = make_float4(0.f, 0.f, 0.f, 0.f);

    const float g = gain[s];

    // c[q] = -a[q-1] (q=1..22), c[23]=c[24]=0
    float c[25];
    #pragma unroll
    for (int p = 0; p < Pn; ++p) c[p + 1] = -a[s * Pn + p];
    c[23] = 0.0f; c[24] = 0.0f;
    const float c1 = c[1], c2 = c[2], c3 = c[3];

    // CA[k] = (c_{2k+1}, c_{2k+2}),  CE[k] = (c_{2k+2}, c_{2k+3})
    // H[k]  = (y_{t-2k-1}, y_{t-2k-2})
    ull CA[11], CE[11], H[11];
    #pragma unroll
    for (int k = 0; k < 11; ++k) {
        CA[k] = pk2(c[2 * k + 1], c[2 * k + 2]);
        CE[k] = pk2(c[2 * k + 2], c[2 * k + 3]);
        H[k]  = 0ull;
    }
    __syncthreads();

    const float* __restrict__ exb = ex + b * Tn;
    const int tbase = warp ? 384 : 0;
    const int emit0 = warp ? EMIT1 : 0;

    // prefetch chunk 0 (coalesced: lane sweeps time, r sweeps frames)
    float xr[32];
    #pragma unroll
    for (int r = 0; r < 32; ++r) {
        int idx = (f0 + r) * HOP + tbase + lane - PADL;
        xr[r] = ((unsigned)idx < (unsigned)Tn) ? exb[idx] : 0.0f;
    }

    for (int cc = 0; cc < NCHUNK; ++cc) {
        const int t0 = tbase + 32 * cc;

        // commit prefetched chunk to this warp's buffer
        #pragma unroll
        for (int r = 0; r < 32; ++r) buf[r * BUFSTRIDE + lane] = xr[r];
        __syncwarp();

        // prefetch next chunk; latency hides under recurrence
        if (cc < NCHUNK - 1) {
            const int t1 = t0 + 32;
            #pragma unroll
            for (int r = 0; r < 32; ++r) {
                int idx = (f0 + r) * HOP + t1 + lane - PADL;
                xr[r] = ((unsigned)idx < (unsigned)Tn) ? exb[idx] : 0.0f;
            }
        }

        // 8 blocks x 4 samples; buf row consumed and overwritten in place
        float* xrow = buf + lane * BUFSTRIDE;
        #pragma unroll
        for (int bk = 0; bk < 8; ++bk) {
            const float4 xv = *(const float4*)(xrow + 4 * bk);

            // dot A0 (y0): CA[k]*H[k], even/odd chains, H[0] last
            ull a0 = mul2_(CA[10], H[10]);
            a0 = fma2_(CA[8], H[8], a0);
            a0 = fma2_(CA[6], H[6], a0);
            a0 = fma2_(CA[4], H[4], a0);
            a0 = fma2_(CA[2], H[2], a0);
            ull a0o = mul2_(CA[9], H[9]);
            a0o = fma2_(CA[7], H[7], a0o);
            a0o = fma2_(CA[5], H[5], a0o);
            a0o = fma2_(CA[3], H[3], a0o);
            a0o = fma2_(CA[1], H[1], a0o);
            a0 = fma2_(CA[0], H[0], a0);
            const ull dA0 = add2_(a0, a0o);

            // dot E0 (y1): CE[k]*H[k]
            ull e0 = mul2_(CE[10], H[10]);
            e0 = fma2_(CE[8], H[8], e0);
            e0 = fma2_(CE[6], H[6], e0);
            e0 = fma2_(CE[4], H[4], e0);
            e0 = fma2_(CE[2], H[2], e0);
            ull e0o = mul2_(CE[9], H[9]);
            e0o = fma2_(CE[7], H[7], e0o);
            e0o = fma2_(CE[5], H[5], e0o);
            e0o = fma2_(CE[3], H[3], e0o);
            e0o = fma2_(CE[1], H[1], e0o);
            e0 = fma2_(CE[0], H[0], e0);
            const ull dE0 = add2_(e0, e0o);

            // dot A1 (y2): CA[k+1]*H[k], k=0..9, H[0] term last
            ull a1 = mul2_(CA[10], H[9]);
            a1 = fma2_(CA[8], H[7], a1);
            a1 = fma2_(CA[6], H[5], a1);
            a1 = fma2_(CA[4], H[3], a1);
            a1 = fma2_(CA[2], H[1], a1);
            ull a1o = mul2_(CA[9], H[8]);
            a1o = fma2_(CA[7], H[6], a1o);
            a1o = fma2_(CA[5], H[4], a1o);
            a1o = fma2_(CA[3], H[2], a1o);
            a1o = fma2_(CA[1], H[0], a1o);
            const ull dA1 = add2_(a1, a1o);

            // dot E1 (y3): CE[k+1]*H[k], k=0..9, H[0] term last
            ull e1 = mul2_(CE[10], H[9]);
            e1 = fma2_(CE[8], H[7], e1);
            e1 = fma2_(CE[6], H[5], e1);
            e1 = fma2_(CE[4], H[3], e1);
            e1 = fma2_(CE[2], H[1], e1);
            ull e1o = mul2_(CE[9], H[8]);
            e1o = fma2_(CE[7], H[6], e1o);
            e1o = fma2_(CE[5], H[4], e1o);
            e1o = fma2_(CE[3], H[2], e1o);
            e1o = fma2_(CE[1], H[0], e1o);
            const ull dE1 = add2_(e1, e1o);

            float lo0, hi0, lo1, hi1, lo2, hi2, lo3, hi3;
            upk2(lo0, hi0, dA0);
            upk2(lo1, hi1, dE0);
            upk2(lo2, hi2, dA1);
            upk2(lo3, hi3, dE1);
            const float sA0 = lo0 + hi0;
            const float sE0 = lo1 + hi1;
            const float sA1 = lo2 + hi2;
            const float sE1 = lo3 + hi3;

            // off-path precomputes (ready before y0 lands)
            const float p1 = fmaf(g, xv.y, sE0);
            const float p2 = fmaf(g, xv.z, sA1);
            const float p3 = fmaf(g, xv.w, sE1);

            const float y0 = fmaf(g, xv.x, sA0);
            const float y1 = fmaf(c1, y0, p1);
            const float y2 = fmaf(c2, y0, fmaf(c1, y1, p2));
            const float y3 = fmaf(c3, y0, fmaf(c2, y1, fmaf(c1, y2, p3)));

            *(float4*)(xrow + 4 * bk) = make_float4(y0, y1, y2, y3);

            // shift history by two pairs
            #pragma unroll
            for (int k = 10; k >= 2; --k) H[k] = H[k - 2];
            H[1] = pk2(y1, y0);
            H[0] = pk2(y3, y2);
        }
        __syncwarp();

        // per-warp windowed OLA accumulate (emit range only)
        if (cc >= emit0) {
            const float wv = hannf(t0 + lane);
            #pragma unroll
            for (int r = 0; r < 32; ++r)
                acc[r * HOP + t0 + lane] += buf[r * BUFSTRIDE + lane] * wv;
        }
        __syncwarp();

        // bound inter-warp round-skew to <= 3 (collision needs skew==4 mod 8)
        if ((cc & 3) == 3) __syncthreads();
    }
    __syncthreads();

    // interior [768, 8192): all 4 contributions local; norm == 2 exactly
    float* __restrict__ outb = out + (size_t)b * Tn + ww * 8192 + 384;
    const float4* __restrict__ acc4 = (const float4*)(acc + STRIPL);
    for (int i = threadIdx.x; i < (8192 - STRIPL) / 4; i += 64) {
        float4 v = acc4[i];
        v.x *= 0.5f; v.y *= 0.5f; v.z *= 0.5f; v.w *= 0.5f;
        ((float4*)outb)[i] = v;
    }
    // seams for kernel 2
    for (int j = threadIdx.x; j < STRIPL; j += 64) {
        d_strip_lo[gw][j] = acc[j];
        d_strip_hi[gw][j] = acc[8192 + j];
    }
}

// ---------------------------------------------------------------------------
// Kernel 2: resolve seams. One block per region, 192 threads, float4/thread.
//   Non-edge seams have norm == 2 exactly; batch edges use hann norms.
// ---------------------------------------------------------------------------
__global__ void __launch_bounds__(192)
strip_kernel(float* __restrict__ out) {
    const int rg = blockIdx.x;
    const int q  = threadIdx.x;        // float4 index 0..191

    if (rg < NGRP) {
        const int w  = rg;
        const int ww = w & 31;
        const int bI = w >> 5;
        const int pbase = ww * 8192;
        const float4 lo4 = ((const float4*)d_strip_lo[w])[q];
        if (ww > 0) {                  // interior seam: norm exactly 2
            const float4 hi4 = ((const float4*)d_strip_hi[w - 1])[q];
            float4 v;
            v.x = (lo4.x + hi4.x) * 0.5f;
            v.y = (lo4.y + hi4.y) * 0.5f;
            v.z = (lo4.z + hi4.z) * 0.5f;
            v.w = (lo4.w + hi4.w) * 0.5f;
            *(float4*)(out + (size_t)bI * Tn + pbase + 4 * q - PADL) = v;
            return;
        }
        // batch-leading edge: per element with window norms
        const float sv[4] = {lo4.x, lo4.y, lo4.z, lo4.w};
        #pragma unroll
        for (int e = 0; e < 4; ++e) {
            const int p = pbase + 4 * q + e;
            const int o = p - PADL;
            if ((unsigned)o >= (unsigned)Tn) continue;
            const int fhi = p >> 8;
            float norm = 0.0f;
            #pragma unroll
            for (int k = 0; k < 4; ++k) {
                const int ff = fhi - k;
                if (ff >= 0 && ff < Fn) norm += hannf(p - ff * HOP);
            }
            out[(size_t)bI * Tn + o] = sv[e] / norm;
        }
    } else {
        const int w = ((rg - NGRP) << 5) | 31;   // batch-trailing edge
        const int bI = w >> 5;
        const int pbase = 32 * 8192;
        const float4 hi4 = ((const float4*)d_strip_hi[w])[q];
        const float sv[4] = {hi4.x, hi4.y, hi4.z, hi4.w};
        #pragma unroll
        for (int e = 0; e < 4; ++e) {
            const int p = pbase + 4 * q + e;
            const int o = p - PADL;
            if ((unsigned)o >= (unsigned)Tn) continue;
            const int fhi = p >> 8;
            float norm = 0.0f;
            #pragma unroll
            for (int k = 0; k < 4; ++k) {
                const int ff = fhi - k;
                if (ff >= 0 && ff < Fn) norm += hannf(p - ff * HOP);
            }
            out[(size_t)bI * Tn + o] = sv[e] / norm;
        }
    }
}

// ---------------------------------------------------------------------------
extern "C" void kernel_launch(void* const* d_in, const int* in_sizes, int n_in,
                              void* d_out, int out_size) {
    const float* ex   = (const float*)d_in[0];
    const float* gain = (const float*)d_in[1];
    const float* a    = (const float*)d_in[2];
    float* out = (float*)d_out;

    cudaFuncSetAttribute(lpc_ola_kernel,
                         cudaFuncAttributeMaxDynamicSharedMemorySize, SMEM_BYTES);
    lpc_ola_kernel<<<NGRP, 64, SMEM_BYTES>>>(ex, gain, a, out);
    strip_kernel<<<NGRP + Bn, 192>>>(out);
}